// round 4
// baseline (speedup 1.0000x reference)
#include <cuda_runtime.h>
#include <cstdint>
#include <math.h>

// ---------------------------------------------------------------------------
// Problem constants
// ---------------------------------------------------------------------------
#define RNG_PARTITIONABLE 1   // modern JAX (>=0.5) default

constexpr int BATCH = 4, SEQ = 1024, DM = 1024, NH = 16, DK = 64, DFF = 4096;
constexpr int NSAMP = 35;                 // min(5*ceil(log(1024)), 1024)
constexpr int NTOP  = 35;
constexpr int ROWS  = BATCH * SEQ;        // 4096
constexpr size_t NELEM = (size_t)ROWS * DM;   // 4,194,304
constexpr int IDX_N = SEQ * NSAMP;        // 35840
constexpr int IDX_HALF = IDX_N / 2;       // 17920

// ---------------------------------------------------------------------------
// Static device scratch (no allocations allowed)
// ---------------------------------------------------------------------------
__device__ float g_q[NELEM];
__device__ float g_k[NELEM];
__device__ float g_v[NELEM];
__device__ float g_ctx[NELEM];
__device__ float g_xin[NELEM];
__device__ float g_x1[NELEM];
__device__ float g_x2[NELEM];
__device__ float g_h[(size_t)ROWS * DFF];
__device__ float g_M[BATCH * NH * SEQ];
__device__ float g_vmean[BATCH * NH * DK];
__device__ int   g_top[BATCH * NH * NTOP];
__device__ int   g_idx[IDX_N];
__device__ float g_mu[DM];
__device__ float g_rstd[DM];

// ---------------------------------------------------------------------------
// TF32 input rounding (matches tensor-core TF32 GEMM input conversion)
// ---------------------------------------------------------------------------
__device__ __forceinline__ float tf32r(float x) {
    uint32_t u;
    asm("cvt.rna.tf32.f32 %0, %1;" : "=r"(u) : "f"(x));
    return __uint_as_float(u);
}

// ---------------------------------------------------------------------------
// threefry2x32 (Random123 / JAX reference)
// ---------------------------------------------------------------------------
__host__ __device__ __forceinline__ void tf2x32(uint32_t k0, uint32_t k1,
                                                uint32_t x0, uint32_t x1,
                                                uint32_t &o0, uint32_t &o1) {
    uint32_t ks2 = k0 ^ k1 ^ 0x1BD11BDAu;
    x0 += k0; x1 += k1;
#define TF_R(r) { x0 += x1; x1 = (x1 << (r)) | (x1 >> (32 - (r))); x1 ^= x0; }
    TF_R(13) TF_R(15) TF_R(26) TF_R(6)
    x0 += k1; x1 += ks2 + 1u;
    TF_R(17) TF_R(29) TF_R(16) TF_R(24)
    x0 += ks2; x1 += k0 + 2u;
    TF_R(13) TF_R(15) TF_R(26) TF_R(6)
    x0 += k0; x1 += k1 + 3u;
    TF_R(17) TF_R(29) TF_R(16) TF_R(24)
    x0 += k1; x1 += ks2 + 4u;
    TF_R(13) TF_R(15) TF_R(26) TF_R(6)
    x0 += ks2; x1 += k0 + 5u;
#undef TF_R
    o0 = x0; o1 = x1;
}

// JAX randint(rng,(1024,35),0,1024):
//   k1,k2 = split(rng); span=1024 pow2 => multiplier=0 =>
//   idx = random_bits(k2, 32, (1024,35)) & 1023
// (ka,kb) passed here is k2 = split(rng)[1], computed on host.
__global__ void make_idx_kernel(uint32_t ka, uint32_t kb, int* __restrict__ out) {
    int j = blockIdx.x * blockDim.x + threadIdx.x;
    if (j >= IDX_N) return;
    uint32_t o0, o1;
#if RNG_PARTITIONABLE
    // bits[j] = xor of the two outputs at 64-bit counter j (hi=0)
    tf2x32(ka, kb, 0u, (uint32_t)j, o0, o1);
    out[j] = (int)((o0 ^ o1) & 1023u);
#else
    // legacy bits: threefry_2x32(key, iota(35840)) halves-pairing
    if (j < IDX_HALF) {
        tf2x32(ka, kb, (uint32_t)j, (uint32_t)(IDX_HALF + j), o0, o1);
        out[j] = (int)(o0 & 1023u);
    } else {
        tf2x32(ka, kb, (uint32_t)(j - IDX_HALF), (uint32_t)j, o0, o1);
        out[j] = (int)(o1 & 1023u);
    }
#endif
}

// ---------------------------------------------------------------------------
// Tiled GEMM, TF32-rounded inputs, fp32 accumulate:
// C[M,N] = tf32(A[M,K]) @ tf32(B[K,N]) (+bias) (gelu?) (+resid)
// ---------------------------------------------------------------------------
#define GBM 64
#define GBN 64
#define GBK 16

__global__ __launch_bounds__(256)
void gemm_kernel(const float* __restrict__ A, const float* __restrict__ B,
                 const float* __restrict__ bias, const float* __restrict__ resid,
                 float* __restrict__ C, int M, int N, int K, int act) {
    __shared__ float As[GBK][GBM];
    __shared__ float Bs[GBK][GBN];
    const int tid = threadIdx.x;
    const int tx = tid & 15, ty = tid >> 4;
    const int row0 = blockIdx.y * GBM;
    const int col0 = blockIdx.x * GBN;

    float acc[4][4] = {};

    for (int k0 = 0; k0 < K; k0 += GBK) {
#pragma unroll
        for (int i = 0; i < 4; i++) {
            int e = tid + i * 256;
            int m = e >> 4, kk = e & 15;     // A tile 64x16
            As[kk][m] = tf32r(A[(size_t)(row0 + m) * K + (k0 + kk)]);
        }
#pragma unroll
        for (int i = 0; i < 4; i++) {
            int e = tid + i * 256;
            int kk = e >> 6, n = e & 63;     // B tile 16x64
            Bs[kk][n] = tf32r(B[(size_t)(k0 + kk) * N + (col0 + n)]);
        }
        __syncthreads();
#pragma unroll
        for (int kk = 0; kk < GBK; kk++) {
            float a[4], b[4];
#pragma unroll
            for (int i = 0; i < 4; i++) a[i] = As[kk][ty * 4 + i];
#pragma unroll
            for (int j = 0; j < 4; j++) b[j] = Bs[kk][tx * 4 + j];
#pragma unroll
            for (int i = 0; i < 4; i++)
#pragma unroll
                for (int j = 0; j < 4; j++) acc[i][j] += a[i] * b[j];
        }
        __syncthreads();
    }

#pragma unroll
    for (int i = 0; i < 4; i++) {
#pragma unroll
        for (int j = 0; j < 4; j++) {
            int m = row0 + ty * 4 + i;
            int n = col0 + tx * 4 + j;
            float vv = acc[i][j];
            if (bias) vv += bias[n];
            if (act) vv = 0.5f * vv * (1.0f + erff(vv * 0.70710678118654752f));
            if (resid) vv += resid[(size_t)m * N + n];
            C[(size_t)m * N + n] = vv;
        }
    }
}

// ---------------------------------------------------------------------------
// M[b,h,l] = max_s(q_l . k_idx[l,s]) - sum_s(q_l . k_idx[l,s]) / SEQ
// one warp per (b,h,l). fp32 (XLA fuses this tiny batched dot; no TF32).
// ---------------------------------------------------------------------------
__global__ void compute_M_kernel(const float* __restrict__ Q, const float* __restrict__ K,
                                 const int* __restrict__ idx, float* __restrict__ Mout) {
    int bhl = blockIdx.x;
    int l = bhl & (SEQ - 1);
    int bh = bhl >> 10;
    int h = bh & (NH - 1);
    int b = bh >> 4;
    int lane = threadIdx.x;

    const float* q = Q + ((size_t)(b * SEQ + l)) * DM + h * DK;
    float q0 = q[lane], q1 = q[lane + 32];
    float mx = -1e38f, sm = 0.0f;
    const int* row = idx + l * NSAMP;
#pragma unroll 1
    for (int s = 0; s < NSAMP; s++) {
        int ki = row[s];
        const float* kr = K + ((size_t)(b * SEQ + ki)) * DM + h * DK;
        float p = q0 * kr[lane] + q1 * kr[lane + 32];
#pragma unroll
        for (int o = 16; o; o >>= 1) p += __shfl_xor_sync(0xffffffffu, p, o);
        mx = fmaxf(mx, p);
        sm += p;
    }
    if (lane == 0) Mout[bhl] = mx - sm * (1.0f / (float)SEQ);
}

// ---------------------------------------------------------------------------
// top-35 per (b,h): iterative argmax, ties -> lower index (lax.top_k order)
// ---------------------------------------------------------------------------
__global__ void topk_kernel(const float* __restrict__ Min, int* __restrict__ top) {
    int bh = blockIdx.x;
    int tid = threadIdx.x;
    __shared__ float vals[SEQ];
    __shared__ float rv[256];
    __shared__ int   ri[256];

    for (int i = tid; i < SEQ; i += 256) vals[i] = Min[(size_t)bh * SEQ + i];
    __syncthreads();

    for (int u = 0; u < NTOP; u++) {
        float bv = -1e38f; int bi = 0x7fffffff;
        for (int i = tid; i < SEQ; i += 256) {
            float vv = vals[i];
            if (vv > bv || (vv == bv && i < bi)) { bv = vv; bi = i; }
        }
        rv[tid] = bv; ri[tid] = bi;
        __syncthreads();
        for (int o = 128; o; o >>= 1) {
            if (tid < o) {
                if (rv[tid + o] > rv[tid] ||
                    (rv[tid + o] == rv[tid] && ri[tid + o] < ri[tid])) {
                    rv[tid] = rv[tid + o]; ri[tid] = ri[tid + o];
                }
            }
            __syncthreads();
        }
        if (tid == 0) { top[bh * NTOP + u] = ri[0]; vals[ri[0]] = -1e38f; }
        __syncthreads();
    }
}

// ---------------------------------------------------------------------------
// vmean[b,h,d] = mean over keys of V (fp32 reduction)
// ---------------------------------------------------------------------------
__global__ void vmean_kernel(const float* __restrict__ V, float* __restrict__ vmean) {
    int bh = blockIdx.x;
    int b = bh >> 4, h = bh & (NH - 1);
    int d = threadIdx.x;  // 64
    const float* base = V + ((size_t)b * SEQ) * DM + h * DK + d;
    float s = 0.0f;
    for (int i = 0; i < SEQ; i++) s += base[(size_t)i * DM];
    vmean[bh * DK + d] = s * (1.0f / (float)SEQ);
}

// ctx[b,s,h*64+d] = vmean[b,h,d]   (broadcast fill, (B,L,H*D) layout)
__global__ void fill_ctx_kernel(const float* __restrict__ vmean, float* __restrict__ ctx) {
    size_t i = (size_t)blockIdx.x * 256 + threadIdx.x;
    int c = (int)(i & (DM - 1));
    int b = (int)(i >> 20);           // i / (SEQ*DM)
    int h = c >> 6, d = c & 63;
    ctx[i] = vmean[(b * NH + h) * DK + d];
}

// ---------------------------------------------------------------------------
// scores + softmax + update-scatter for one (b,h,u).
// scores & upd einsums are real GEMMs in XLA -> TF32-rounded inputs.
// ---------------------------------------------------------------------------
__global__ __launch_bounds__(256)
void attn_update_kernel(const float* __restrict__ Q, const float* __restrict__ K,
                        const float* __restrict__ V, const int* __restrict__ top,
                        float* __restrict__ ctx) {
    int u  = blockIdx.x % NTOP;
    int bh = blockIdx.x / NTOP;
    int h = bh & (NH - 1), b = bh >> 4;
    int qrow = top[bh * NTOP + u];

    __shared__ float qs[DK];
    __shared__ float sc[SEQ];
    __shared__ float sred[256];
    __shared__ float us[256];

    int tid = threadIdx.x;
    int lane = tid & 31, warp = tid >> 5;

    if (tid < DK) qs[tid] = tf32r(Q[((size_t)(b * SEQ + qrow)) * DM + h * DK + tid]);
    __syncthreads();

    // scores: one warp per key row, coalesced; TF32 inputs, fp32 accumulate
    for (int key = warp; key < SEQ; key += 8) {
        const float* kr = K + ((size_t)(b * SEQ + key)) * DM + h * DK;
        float p = qs[lane] * tf32r(kr[lane]) + qs[lane + 32] * tf32r(kr[lane + 32]);
#pragma unroll
        for (int o = 16; o; o >>= 1) p += __shfl_xor_sync(0xffffffffu, p, o);
        if (lane == 0) sc[key] = p * 0.125f;   // 1/sqrt(64)
    }
    __syncthreads();

    // softmax max
    float m = -1e38f;
    for (int i = tid; i < SEQ; i += 256) m = fmaxf(m, sc[i]);
    sred[tid] = m; __syncthreads();
    for (int o = 128; o; o >>= 1) { if (tid < o) sred[tid] = fmaxf(sred[tid], sred[tid + o]); __syncthreads(); }
    float mx = sred[0];
    __syncthreads();

    // exp + sum
    float s = 0.0f;
    for (int i = tid; i < SEQ; i += 256) { float e = expf(sc[i] - mx); sc[i] = e; s += e; }
    sred[tid] = s; __syncthreads();
    for (int o = 128; o; o >>= 1) { if (tid < o) sred[tid] += sred[tid + o]; __syncthreads(); }
    float denom = sred[0];
    __syncthreads();

    // upd = tf32(attn) @ tf32(V): normalize FIRST, then round (matches ref order)
    float rdenom = 1.0f / denom;
    int d = tid & 63, g = tid >> 6;
    float acc = 0.0f;
    for (int key = g; key < SEQ; key += 4) {
        float p = tf32r(sc[key] * rdenom);
        acc += p * tf32r(V[((size_t)(b * SEQ + key)) * DM + h * DK + d]);
    }
    us[g * 64 + d] = acc;
    __syncthreads();

    if (tid < DK) {
        float r = us[tid] + us[64 + tid] + us[128 + tid] + us[192 + tid];
        ctx[((size_t)(b * SEQ + qrow)) * DM + h * DK + tid] = r;
    }
}

// ---------------------------------------------------------------------------
// BatchNorm over (B,S) per channel: two-pass, fp32
// ---------------------------------------------------------------------------
__global__ void bn_stats_kernel(const float* __restrict__ x,
                                float* __restrict__ mu, float* __restrict__ rstd) {
    int c = blockIdx.x;
    int tid = threadIdx.x;
    __shared__ float sm[256];
    __shared__ float meansh;

    float s = 0.0f;
    for (int i = tid; i < ROWS; i += 256) s += x[(size_t)i * DM + c];
    sm[tid] = s; __syncthreads();
    for (int o = 128; o; o >>= 1) { if (tid < o) sm[tid] += sm[tid + o]; __syncthreads(); }
    if (tid == 0) meansh = sm[0] * (1.0f / (float)ROWS);
    __syncthreads();
    float mean = meansh;

    float v = 0.0f;
    for (int i = tid; i < ROWS; i += 256) { float d = x[(size_t)i * DM + c] - mean; v += d * d; }
    sm[tid] = v; __syncthreads();
    for (int o = 128; o; o >>= 1) { if (tid < o) sm[tid] += sm[tid + o]; __syncthreads(); }
    if (tid == 0) {
        mu[c] = mean;
        rstd[c] = rsqrtf(sm[0] * (1.0f / (float)ROWS) + 1e-5f);
    }
}

__global__ void bn_apply_kernel(const float* __restrict__ x, const float* __restrict__ mu,
                                const float* __restrict__ rstd, const float* __restrict__ g,
                                const float* __restrict__ bta, float* __restrict__ y) {
    size_t i = (size_t)blockIdx.x * 256 + threadIdx.x;
    int c = (int)(i & (DM - 1));
    y[i] = (x[i] - mu[c]) * rstd[c] * g[c] + bta[c];
}

// ---------------------------------------------------------------------------
// Launch
// ---------------------------------------------------------------------------
static void run_gemm(const float* A, const float* B, const float* bias,
                     const float* resid, float* C, int M, int N, int K, int act) {
    dim3 grid(N / GBN, M / GBM);
    gemm_kernel<<<grid, 256>>>(A, B, bias, resid, C, M, N, K, act);
}

extern "C" void kernel_launch(void* const* d_in, const int* in_sizes, int n_in,
                              void* d_out, int out_size) {
    const float* tgt   = (const float*)d_in[0];
    const float* mem   = (const float*)d_in[1];
    const float* sa_wq = (const float*)d_in[2];
    const float* sa_bq = (const float*)d_in[3];
    const float* sa_wk = (const float*)d_in[4];
    const float* sa_bk = (const float*)d_in[5];
    const float* sa_wv = (const float*)d_in[6];
    const float* sa_bv = (const float*)d_in[7];
    const float* sa_wo = (const float*)d_in[8];
    const float* sa_bo = (const float*)d_in[9];
    const float* ca_wq = (const float*)d_in[10];
    const float* ca_bq = (const float*)d_in[11];
    const float* ca_wk = (const float*)d_in[12];
    const float* ca_bk = (const float*)d_in[13];
    const float* ca_wv = (const float*)d_in[14];
    const float* ca_bv = (const float*)d_in[15];
    const float* ca_wo = (const float*)d_in[16];
    const float* ca_bo = (const float*)d_in[17];
    const float* w1    = (const float*)d_in[18];
    const float* b1    = (const float*)d_in[19];
    const float* w2    = (const float*)d_in[20];
    const float* b2    = (const float*)d_in[21];
    const float* bn1_g = (const float*)d_in[22];
    const float* bn1_b = (const float*)d_in[23];
    const float* bn2_g = (const float*)d_in[24];
    const float* bn2_b = (const float*)d_in[25];
    const float* bn3_g = (const float*)d_in[26];
    const float* bn3_b = (const float*)d_in[27];
    float* out = (float*)d_out;

    float *q, *k, *v, *ctx, *xin, *x1, *x2, *hbuf, *Mb, *vm, *mu, *rs;
    int *top, *idx;
    cudaGetSymbolAddress((void**)&q,    g_q);
    cudaGetSymbolAddress((void**)&k,    g_k);
    cudaGetSymbolAddress((void**)&v,    g_v);
    cudaGetSymbolAddress((void**)&ctx,  g_ctx);
    cudaGetSymbolAddress((void**)&xin,  g_xin);
    cudaGetSymbolAddress((void**)&x1,   g_x1);
    cudaGetSymbolAddress((void**)&x2,   g_x2);
    cudaGetSymbolAddress((void**)&hbuf, g_h);
    cudaGetSymbolAddress((void**)&Mb,   g_M);
    cudaGetSymbolAddress((void**)&vm,   g_vmean);
    cudaGetSymbolAddress((void**)&top,  g_top);
    cudaGetSymbolAddress((void**)&idx,  g_idx);
    cudaGetSymbolAddress((void**)&mu,   g_mu);
    cudaGetSymbolAddress((void**)&rs,   g_rstd);

    // -----------------------------------------------------------------------
    // Key derivation. root = key(42) = (0,42).
    // k1_attn, k2_attn = split(root).
    // randint(rng,...) internally does s1,s2 = split(rng) and (span pow2)
    // uses only s2 for lower_bits. We pass s2 to make_idx_kernel.
    // -----------------------------------------------------------------------
    uint32_t r1a, r1b, r2a, r2b;        // attention rngs (k1_attn, k2_attn)
    uint32_t s1a, s1b, s2a, s2b;        // randint sub-keys (split(rng)[1])
#if RNG_PARTITIONABLE
    tf2x32(0u, 42u, 0u, 0u, r1a, r1b);  // split(root)[0]
    tf2x32(0u, 42u, 0u, 1u, r2a, r2b);  // split(root)[1]
    tf2x32(r1a, r1b, 0u, 1u, s1a, s1b); // split(r1)[1]
    tf2x32(r2a, r2b, 0u, 1u, s2a, s2b); // split(r2)[1]
#else
    {
        uint32_t a0, b0, a1, b1;
        // split(root): counts [0,1,2,3] halves (0,2),(1,3)
        tf2x32(0u, 42u, 0u, 2u, a0, b0);
        tf2x32(0u, 42u, 1u, 3u, a1, b1);
        r1a = a0; r1b = a1;             // (o0(0,2), o0(1,3))
        r2a = b0; r2b = b1;             // (o1(0,2), o1(1,3))
        // split(r1)[1]
        tf2x32(r1a, r1b, 0u, 2u, a0, b0);
        tf2x32(r1a, r1b, 1u, 3u, a1, b1);
        s1a = b0; s1b = b1;
        // split(r2)[1]
        tf2x32(r2a, r2b, 0u, 2u, a0, b0);
        tf2x32(r2a, r2b, 1u, 3u, a1, b1);
        s2a = b0; s2b = b1;
    }
#endif

    const int ELT_BLKS = (int)(NELEM / 256);
    const int IDX_BLKS = (IDX_N + 255) / 256;

    // ================= Self-attention =================
    make_idx_kernel<<<IDX_BLKS, 256>>>(s1a, s1b, idx);
    run_gemm(tgt, sa_wq, sa_bq, nullptr, q, ROWS, DM, DM, 0);
    run_gemm(tgt, sa_wk, sa_bk, nullptr, k, ROWS, DM, DM, 0);
    run_gemm(tgt, sa_wv, sa_bv, nullptr, v, ROWS, DM, DM, 0);
    compute_M_kernel<<<BATCH * NH * SEQ, 32>>>(q, k, idx, Mb);
    topk_kernel<<<BATCH * NH, 256>>>(Mb, top);
    vmean_kernel<<<BATCH * NH, DK>>>(v, vm);
    fill_ctx_kernel<<<ELT_BLKS, 256>>>(vm, ctx);
    attn_update_kernel<<<BATCH * NH * NTOP, 256>>>(q, k, v, top, ctx);
    run_gemm(ctx, sa_wo, sa_bo, tgt, xin, ROWS, DM, DM, 0);   // xin = tgt + t2
    bn_stats_kernel<<<DM, 256>>>(xin, mu, rs);
    bn_apply_kernel<<<ELT_BLKS, 256>>>(xin, mu, rs, bn1_g, bn1_b, x1);

    // ================= Cross-attention =================
    make_idx_kernel<<<IDX_BLKS, 256>>>(s2a, s2b, idx);
    run_gemm(x1,  ca_wq, ca_bq, nullptr, q, ROWS, DM, DM, 0);
    run_gemm(mem, ca_wk, ca_bk, nullptr, k, ROWS, DM, DM, 0);
    run_gemm(mem, ca_wv, ca_bv, nullptr, v, ROWS, DM, DM, 0);
    compute_M_kernel<<<BATCH * NH * SEQ, 32>>>(q, k, idx, Mb);
    topk_kernel<<<BATCH * NH, 256>>>(Mb, top);
    vmean_kernel<<<BATCH * NH, DK>>>(v, vm);
    fill_ctx_kernel<<<ELT_BLKS, 256>>>(vm, ctx);
    attn_update_kernel<<<BATCH * NH * NTOP, 256>>>(q, k, v, top, ctx);
    run_gemm(ctx, ca_wo, ca_bo, x1, xin, ROWS, DM, DM, 0);    // xin = x1 + t2
    bn_stats_kernel<<<DM, 256>>>(xin, mu, rs);
    bn_apply_kernel<<<ELT_BLKS, 256>>>(xin, mu, rs, bn2_g, bn2_b, x2);

    // ================= FFN =================
    run_gemm(x2, w1, b1, nullptr, hbuf, ROWS, DFF, DM, 1);    // gelu(x2@w1+b1)
    run_gemm(hbuf, w2, b2, x2, xin, ROWS, DM, DFF, 0);        // xin = x2 + ffn
    bn_stats_kernel<<<DM, 256>>>(xin, mu, rs);
    bn_apply_kernel<<<ELT_BLKS, 256>>>(xin, mu, rs, bn3_g, bn3_b, out);
}

// round 5
// speedup vs baseline: 2.5440x; 2.5440x over previous
#include <cuda_runtime.h>
#include <cstdint>
#include <math.h>

// ---------------------------------------------------------------------------
// Problem constants
// ---------------------------------------------------------------------------
#define RNG_PARTITIONABLE 1   // confirmed passing config -- do not change

constexpr int BATCH = 4, SEQ = 1024, DM = 1024, NH = 16, DK = 64, DFF = 4096;
constexpr int NSAMP = 35;
constexpr int NTOP  = 35;
constexpr int ROWS  = BATCH * SEQ;        // 4096
constexpr size_t NELEM = (size_t)ROWS * DM;
constexpr int IDX_N = SEQ * NSAMP;        // 35840
constexpr int IDX_HALF = IDX_N / 2;

// ---------------------------------------------------------------------------
// Static device scratch
// ---------------------------------------------------------------------------
__device__ float g_q[NELEM];
__device__ float g_k[NELEM];
__device__ float g_v[NELEM];
__device__ float g_ctx[NELEM];
__device__ float g_xin[NELEM];
__device__ float g_x1[NELEM];
__device__ float g_x2[NELEM];
__device__ float g_h[(size_t)ROWS * DFF];
__device__ float g_M[BATCH * NH * SEQ];
__device__ float g_vmean[BATCH * NH * DK];
__device__ int   g_top[BATCH * NH * NTOP];
__device__ int   g_idx[IDX_N];
__device__ float g_mu[DM];
__device__ float g_rstd[DM];

// ---------------------------------------------------------------------------
// TF32 input rounding (matches tensor-core GEMM input conversion)
// ---------------------------------------------------------------------------
__device__ __forceinline__ float tf32r(float x) {
    uint32_t u;
    asm("cvt.rna.tf32.f32 %0, %1;" : "=r"(u) : "f"(x));
    return __uint_as_float(u);
}

// ---------------------------------------------------------------------------
// threefry2x32
// ---------------------------------------------------------------------------
__host__ __device__ __forceinline__ void tf2x32(uint32_t k0, uint32_t k1,
                                                uint32_t x0, uint32_t x1,
                                                uint32_t &o0, uint32_t &o1) {
    uint32_t ks2 = k0 ^ k1 ^ 0x1BD11BDAu;
    x0 += k0; x1 += k1;
#define TF_R(r) { x0 += x1; x1 = (x1 << (r)) | (x1 >> (32 - (r))); x1 ^= x0; }
    TF_R(13) TF_R(15) TF_R(26) TF_R(6)
    x0 += k1; x1 += ks2 + 1u;
    TF_R(17) TF_R(29) TF_R(16) TF_R(24)
    x0 += ks2; x1 += k0 + 2u;
    TF_R(13) TF_R(15) TF_R(26) TF_R(6)
    x0 += k0; x1 += k1 + 3u;
    TF_R(17) TF_R(29) TF_R(16) TF_R(24)
    x0 += k1; x1 += ks2 + 4u;
    TF_R(13) TF_R(15) TF_R(26) TF_R(6)
    x0 += ks2; x1 += k0 + 5u;
#undef TF_R
    o0 = x0; o1 = x1;
}

// randint: uses split(rng)[1] for lower_bits; span pow2 => & 1023
__global__ void make_idx_kernel(uint32_t ka, uint32_t kb, int* __restrict__ out) {
    int j = blockIdx.x * blockDim.x + threadIdx.x;
    if (j >= IDX_N) return;
    uint32_t o0, o1;
#if RNG_PARTITIONABLE
    tf2x32(ka, kb, 0u, (uint32_t)j, o0, o1);
    out[j] = (int)((o0 ^ o1) & 1023u);
#else
    if (j < IDX_HALF) {
        tf2x32(ka, kb, (uint32_t)j, (uint32_t)(IDX_HALF + j), o0, o1);
        out[j] = (int)(o0 & 1023u);
    } else {
        tf2x32(ka, kb, (uint32_t)(j - IDX_HALF), (uint32_t)j, o0, o1);
        out[j] = (int)(o1 & 1023u);
    }
#endif
}

// ---------------------------------------------------------------------------
// Tensor-core TF32 GEMM: C = tf32(A[M,K]) @ tf32(B[K,N]) (+bias)(gelu?)(+resid)
// 128x128x16 block tile, 8 warps (2x4), warp tile 64x32, m16n8k8 mma.
// ---------------------------------------------------------------------------
constexpr int BM = 128, BN = 128, BK = 16;
constexpr int SSTR = 136;   // smem row stride (floats): conflict-free frags, 16B-aligned

__device__ __forceinline__ void mma_tf32(float c[4], uint32_t a0, uint32_t a1,
                                         uint32_t a2, uint32_t a3,
                                         uint32_t b0, uint32_t b1) {
    asm volatile(
        "mma.sync.aligned.m16n8k8.row.col.f32.tf32.tf32.f32 "
        "{%0,%1,%2,%3}, {%4,%5,%6,%7}, {%8,%9}, {%0,%1,%2,%3};"
        : "+f"(c[0]), "+f"(c[1]), "+f"(c[2]), "+f"(c[3])
        : "r"(a0), "r"(a1), "r"(a2), "r"(a3), "r"(b0), "r"(b1));
}

__global__ __launch_bounds__(256)
void gemm_tc_kernel(const float* __restrict__ A, const float* __restrict__ B,
                    const float* __restrict__ bias, const float* __restrict__ resid,
                    float* __restrict__ C, int M, int N, int K, int act) {
    __shared__ float As[2][BK][SSTR];   // [k][m]
    __shared__ float Bs[2][BK][SSTR];   // [k][n]

    const int tid  = threadIdx.x;
    const int lane = tid & 31, warp = tid >> 5;
    const int warpM = warp >> 2, warpN = warp & 3;      // 2 x 4
    const int grp = lane >> 2, thr = lane & 3;
    const int row0 = blockIdx.y * BM;
    const int col0 = blockIdx.x * BN;

    float acc[4][4][4];
#pragma unroll
    for (int mt = 0; mt < 4; mt++)
#pragma unroll
        for (int nt = 0; nt < 4; nt++)
#pragma unroll
            for (int i = 0; i < 4; i++) acc[mt][nt][i] = 0.0f;

    // global load mapping: 2 float4 each for A and B per thread
    // A tile: 128 rows x 16 cols; f = tid*2+i: r = f>>2, c4 = f&3
    // B tile: 16 rows x 128 cols; f = tid*2+i: r = f>>5, c4 = f&31
    const int T = K / BK;
    float4 aF[2], bF[2];

    auto loadTile = [&](int t) {
#pragma unroll
        for (int i = 0; i < 2; i++) {
            int f = tid * 2 + i;
            int ar = f >> 2, ac4 = f & 3;
            aF[i] = *(const float4*)&A[(size_t)(row0 + ar) * K + t * BK + ac4 * 4];
            int br = f >> 5, bc4 = f & 31;
            bF[i] = *(const float4*)&B[(size_t)(t * BK + br) * N + col0 + bc4 * 4];
        }
    };
    auto storeTile = [&](int buf) {
#pragma unroll
        for (int i = 0; i < 2; i++) {
            int f = tid * 2 + i;
            int ar = f >> 2, ac4 = f & 3;
            As[buf][ac4 * 4 + 0][ar] = tf32r(aF[i].x);
            As[buf][ac4 * 4 + 1][ar] = tf32r(aF[i].y);
            As[buf][ac4 * 4 + 2][ar] = tf32r(aF[i].z);
            As[buf][ac4 * 4 + 3][ar] = tf32r(aF[i].w);
            int br = f >> 5, bc4 = f & 31;
            float* bp = &Bs[buf][br][bc4 * 4];
            bp[0] = tf32r(bF[i].x); bp[1] = tf32r(bF[i].y);
            bp[2] = tf32r(bF[i].z); bp[3] = tf32r(bF[i].w);
        }
    };

    loadTile(0);
    storeTile(0);
    __syncthreads();

    for (int t = 0; t < T; t++) {
        const int cur = t & 1;
        if (t + 1 < T) loadTile(t + 1);

#pragma unroll
        for (int ks = 0; ks < 2; ks++) {
            const int kk = ks * 8;
            uint32_t a[4][4], b[4][2];
#pragma unroll
            for (int mt = 0; mt < 4; mt++) {
                int mb = warpM * 64 + mt * 16 + grp;
                a[mt][0] = __float_as_uint(As[cur][kk + thr][mb]);
                a[mt][1] = __float_as_uint(As[cur][kk + thr][mb + 8]);
                a[mt][2] = __float_as_uint(As[cur][kk + thr + 4][mb]);
                a[mt][3] = __float_as_uint(As[cur][kk + thr + 4][mb + 8]);
            }
#pragma unroll
            for (int nt = 0; nt < 4; nt++) {
                int nb = warpN * 32 + nt * 8 + grp;
                b[nt][0] = __float_as_uint(Bs[cur][kk + thr][nb]);
                b[nt][1] = __float_as_uint(Bs[cur][kk + thr + 4][nb]);
            }
#pragma unroll
            for (int mt = 0; mt < 4; mt++)
#pragma unroll
                for (int nt = 0; nt < 4; nt++)
                    mma_tf32(acc[mt][nt], a[mt][0], a[mt][1], a[mt][2], a[mt][3],
                             b[nt][0], b[nt][1]);
        }

        if (t + 1 < T) storeTile((t + 1) & 1);
        __syncthreads();
    }

    // epilogue: c frag (m16n8): c0(r=grp,c=thr*2) c1(+1) c2(r=grp+8) c3(+1)
#pragma unroll
    for (int mt = 0; mt < 4; mt++) {
#pragma unroll
        for (int nt = 0; nt < 4; nt++) {
#pragma unroll
            for (int half = 0; half < 2; half++) {
                int m = row0 + warpM * 64 + mt * 16 + grp + half * 8;
                int n = col0 + warpN * 32 + nt * 8 + thr * 2;
#pragma unroll
                for (int c = 0; c < 2; c++) {
                    float vv = acc[mt][nt][half * 2 + c];
                    int nn = n + c;
                    if (bias) vv += bias[nn];
                    if (act) vv = 0.5f * vv * (1.0f + erff(vv * 0.70710678118654752f));
                    if (resid) vv += resid[(size_t)m * N + nn];
                    C[(size_t)m * N + nn] = vv;
                }
            }
        }
    }
}

// ---------------------------------------------------------------------------
// M[b,h,l]: one warp per (b,h,l), fp32
// ---------------------------------------------------------------------------
__global__ void compute_M_kernel(const float* __restrict__ Q, const float* __restrict__ K,
                                 const int* __restrict__ idx, float* __restrict__ Mout) {
    int bhl = blockIdx.x;
    int l = bhl & (SEQ - 1);
    int bh = bhl >> 10;
    int h = bh & (NH - 1);
    int b = bh >> 4;
    int lane = threadIdx.x;

    const float* q = Q + ((size_t)(b * SEQ + l)) * DM + h * DK;
    float q0 = q[lane], q1 = q[lane + 32];
    float mx = -1e38f, sm = 0.0f;
    const int* row = idx + l * NSAMP;
#pragma unroll 1
    for (int s = 0; s < NSAMP; s++) {
        int ki = row[s];
        const float* kr = K + ((size_t)(b * SEQ + ki)) * DM + h * DK;
        float p = q0 * kr[lane] + q1 * kr[lane + 32];
#pragma unroll
        for (int o = 16; o; o >>= 1) p += __shfl_xor_sync(0xffffffffu, p, o);
        mx = fmaxf(mx, p);
        sm += p;
    }
    if (lane == 0) Mout[bhl] = mx - sm * (1.0f / (float)SEQ);
}

// ---------------------------------------------------------------------------
// top-35 per (b,h)
// ---------------------------------------------------------------------------
__global__ void topk_kernel(const float* __restrict__ Min, int* __restrict__ top) {
    int bh = blockIdx.x;
    int tid = threadIdx.x;
    __shared__ float vals[SEQ];
    __shared__ float rv[256];
    __shared__ int   ri[256];

    for (int i = tid; i < SEQ; i += 256) vals[i] = Min[(size_t)bh * SEQ + i];
    __syncthreads();

    for (int u = 0; u < NTOP; u++) {
        float bv = -1e38f; int bi = 0x7fffffff;
        for (int i = tid; i < SEQ; i += 256) {
            float vv = vals[i];
            if (vv > bv || (vv == bv && i < bi)) { bv = vv; bi = i; }
        }
        rv[tid] = bv; ri[tid] = bi;
        __syncthreads();
        for (int o = 128; o; o >>= 1) {
            if (tid < o) {
                if (rv[tid + o] > rv[tid] ||
                    (rv[tid + o] == rv[tid] && ri[tid + o] < ri[tid])) {
                    rv[tid] = rv[tid + o]; ri[tid] = ri[tid + o];
                }
            }
            __syncthreads();
        }
        if (tid == 0) { top[bh * NTOP + u] = ri[0]; vals[ri[0]] = -1e38f; }
        __syncthreads();
    }
}

// ---------------------------------------------------------------------------
// vmean + ctx broadcast fill
// ---------------------------------------------------------------------------
__global__ void vmean_kernel(const float* __restrict__ V, float* __restrict__ vmean) {
    int bh = blockIdx.x;
    int b = bh >> 4, h = bh & (NH - 1);
    int d = threadIdx.x;
    const float* base = V + ((size_t)b * SEQ) * DM + h * DK + d;
    float s = 0.0f;
    for (int i = 0; i < SEQ; i++) s += base[(size_t)i * DM];
    vmean[bh * DK + d] = s * (1.0f / (float)SEQ);
}

__global__ void fill_ctx_kernel(const float* __restrict__ vmean, float* __restrict__ ctx) {
    size_t i = (size_t)blockIdx.x * 256 + threadIdx.x;
    int c = (int)(i & (DM - 1));
    int b = (int)(i >> 20);
    int h = c >> 6, d = c & 63;
    ctx[i] = vmean[(b * NH + h) * DK + d];
}

// ---------------------------------------------------------------------------
// scores + softmax + update-scatter (TF32 inputs for score/upd einsums)
// ---------------------------------------------------------------------------
__global__ __launch_bounds__(256)
void attn_update_kernel(const float* __restrict__ Q, const float* __restrict__ K,
                        const float* __restrict__ V, const int* __restrict__ top,
                        float* __restrict__ ctx) {
    int u  = blockIdx.x % NTOP;
    int bh = blockIdx.x / NTOP;
    int h = bh & (NH - 1), b = bh >> 4;
    int qrow = top[bh * NTOP + u];

    __shared__ float qs[DK];
    __shared__ float sc[SEQ];
    __shared__ float sred[256];
    __shared__ float us[256];

    int tid = threadIdx.x;
    int lane = tid & 31, warp = tid >> 5;

    if (tid < DK) qs[tid] = tf32r(Q[((size_t)(b * SEQ + qrow)) * DM + h * DK + tid]);
    __syncthreads();

    for (int key = warp; key < SEQ; key += 8) {
        const float* kr = K + ((size_t)(b * SEQ + key)) * DM + h * DK;
        float p = qs[lane] * tf32r(kr[lane]) + qs[lane + 32] * tf32r(kr[lane + 32]);
#pragma unroll
        for (int o = 16; o; o >>= 1) p += __shfl_xor_sync(0xffffffffu, p, o);
        if (lane == 0) sc[key] = p * 0.125f;
    }
    __syncthreads();

    float m = -1e38f;
    for (int i = tid; i < SEQ; i += 256) m = fmaxf(m, sc[i]);
    sred[tid] = m; __syncthreads();
    for (int o = 128; o; o >>= 1) { if (tid < o) sred[tid] = fmaxf(sred[tid], sred[tid + o]); __syncthreads(); }
    float mx = sred[0];
    __syncthreads();

    float s = 0.0f;
    for (int i = tid; i < SEQ; i += 256) { float e = expf(sc[i] - mx); sc[i] = e; s += e; }
    sred[tid] = s; __syncthreads();
    for (int o = 128; o; o >>= 1) { if (tid < o) sred[tid] += sred[tid + o]; __syncthreads(); }
    float denom = sred[0];
    __syncthreads();

    float rdenom = 1.0f / denom;
    int d = tid & 63, g = tid >> 6;
    float acc = 0.0f;
    for (int key = g; key < SEQ; key += 4) {
        float p = tf32r(sc[key] * rdenom);
        acc += p * tf32r(V[((size_t)(b * SEQ + key)) * DM + h * DK + d]);
    }
    us[g * 64 + d] = acc;
    __syncthreads();

    if (tid < DK) {
        float r = us[tid] + us[64 + tid] + us[128 + tid] + us[192 + tid];
        ctx[((size_t)(b * SEQ + qrow)) * DM + h * DK + tid] = r;
    }
}

// ---------------------------------------------------------------------------
// BatchNorm (two-pass)
// ---------------------------------------------------------------------------
__global__ void bn_stats_kernel(const float* __restrict__ x,
                                float* __restrict__ mu, float* __restrict__ rstd) {
    int c = blockIdx.x;
    int tid = threadIdx.x;
    __shared__ float sm[256];
    __shared__ float meansh;

    float s = 0.0f;
    for (int i = tid; i < ROWS; i += 256) s += x[(size_t)i * DM + c];
    sm[tid] = s; __syncthreads();
    for (int o = 128; o; o >>= 1) { if (tid < o) sm[tid] += sm[tid + o]; __syncthreads(); }
    if (tid == 0) meansh = sm[0] * (1.0f / (float)ROWS);
    __syncthreads();
    float mean = meansh;

    float v = 0.0f;
    for (int i = tid; i < ROWS; i += 256) { float d = x[(size_t)i * DM + c] - mean; v += d * d; }
    sm[tid] = v; __syncthreads();
    for (int o = 128; o; o >>= 1) { if (tid < o) sm[tid] += sm[tid + o]; __syncthreads(); }
    if (tid == 0) {
        mu[c] = mean;
        rstd[c] = rsqrtf(sm[0] * (1.0f / (float)ROWS) + 1e-5f);
    }
}

__global__ void bn_apply_kernel(const float* __restrict__ x, const float* __restrict__ mu,
                                const float* __restrict__ rstd, const float* __restrict__ g,
                                const float* __restrict__ bta, float* __restrict__ y) {
    size_t i = (size_t)blockIdx.x * 256 + threadIdx.x;
    int c = (int)(i & (DM - 1));
    y[i] = (x[i] - mu[c]) * rstd[c] * g[c] + bta[c];
}

// ---------------------------------------------------------------------------
// Launch
// ---------------------------------------------------------------------------
static void run_gemm(const float* A, const float* B, const float* bias,
                     const float* resid, float* C, int M, int N, int K, int act) {
    dim3 grid(N / BN, M / BM);
    gemm_tc_kernel<<<grid, 256>>>(A, B, bias, resid, C, M, N, K, act);
}

extern "C" void kernel_launch(void* const* d_in, const int* in_sizes, int n_in,
                              void* d_out, int out_size) {
    const float* tgt   = (const float*)d_in[0];
    const float* mem   = (const float*)d_in[1];
    const float* sa_wq = (const float*)d_in[2];
    const float* sa_bq = (const float*)d_in[3];
    const float* sa_wk = (const float*)d_in[4];
    const float* sa_bk = (const float*)d_in[5];
    const float* sa_wv = (const float*)d_in[6];
    const float* sa_bv = (const float*)d_in[7];
    const float* sa_wo = (const float*)d_in[8];
    const float* sa_bo = (const float*)d_in[9];
    const float* ca_wq = (const float*)d_in[10];
    const float* ca_bq = (const float*)d_in[11];
    const float* ca_wk = (const float*)d_in[12];
    const float* ca_bk = (const float*)d_in[13];
    const float* ca_wv = (const float*)d_in[14];
    const float* ca_bv = (const float*)d_in[15];
    const float* ca_wo = (const float*)d_in[16];
    const float* ca_bo = (const float*)d_in[17];
    const float* w1    = (const float*)d_in[18];
    const float* b1    = (const float*)d_in[19];
    const float* w2    = (const float*)d_in[20];
    const float* b2    = (const float*)d_in[21];
    const float* bn1_g = (const float*)d_in[22];
    const float* bn1_b = (const float*)d_in[23];
    const float* bn2_g = (const float*)d_in[24];
    const float* bn2_b = (const float*)d_in[25];
    const float* bn3_g = (const float*)d_in[26];
    const float* bn3_b = (const float*)d_in[27];
    float* out = (float*)d_out;

    float *q, *k, *v, *ctx, *xin, *x1, *x2, *hbuf, *Mb, *vm, *mu, *rs;
    int *top, *idx;
    cudaGetSymbolAddress((void**)&q,    g_q);
    cudaGetSymbolAddress((void**)&k,    g_k);
    cudaGetSymbolAddress((void**)&v,    g_v);
    cudaGetSymbolAddress((void**)&ctx,  g_ctx);
    cudaGetSymbolAddress((void**)&xin,  g_xin);
    cudaGetSymbolAddress((void**)&x1,   g_x1);
    cudaGetSymbolAddress((void**)&x2,   g_x2);
    cudaGetSymbolAddress((void**)&hbuf, g_h);
    cudaGetSymbolAddress((void**)&Mb,   g_M);
    cudaGetSymbolAddress((void**)&vm,   g_vmean);
    cudaGetSymbolAddress((void**)&top,  g_top);
    cudaGetSymbolAddress((void**)&idx,  g_idx);
    cudaGetSymbolAddress((void**)&mu,   g_mu);
    cudaGetSymbolAddress((void**)&rs,   g_rstd);

    // Key derivation. root = key(42) = (0,42).
    // k1_attn, k2_attn = split(root); randint uses split(rng)[1].
    uint32_t r1a, r1b, r2a, r2b;
    uint32_t s1a, s1b, s2a, s2b;
#if RNG_PARTITIONABLE
    tf2x32(0u, 42u, 0u, 0u, r1a, r1b);
    tf2x32(0u, 42u, 0u, 1u, r2a, r2b);
    tf2x32(r1a, r1b, 0u, 1u, s1a, s1b);
    tf2x32(r2a, r2b, 0u, 1u, s2a, s2b);
#else
    {
        uint32_t a0, b0, a1, b1;
        tf2x32(0u, 42u, 0u, 2u, a0, b0);
        tf2x32(0u, 42u, 1u, 3u, a1, b1);
        r1a = a0; r1b = a1;
        r2a = b0; r2b = b1;
        tf2x32(r1a, r1b, 0u, 2u, a0, b0);
        tf2x32(r1a, r1b, 1u, 3u, a1, b1);
        s1a = b0; s1b = b1;
        tf2x32(r2a, r2b, 0u, 2u, a0, b0);
        tf2x32(r2a, r2b, 1u, 3u, a1, b1);
        s2a = b0; s2b = b1;
    }
#endif

    const int ELT_BLKS = (int)(NELEM / 256);
    const int IDX_BLKS = (IDX_N + 255) / 256;

    // ================= Self-attention =================
    make_idx_kernel<<<IDX_BLKS, 256>>>(s1a, s1b, idx);
    run_gemm(tgt, sa_wq, sa_bq, nullptr, q, ROWS, DM, DM, 0);
    run_gemm(tgt, sa_wk, sa_bk, nullptr, k, ROWS, DM, DM, 0);
    run_gemm(tgt, sa_wv, sa_bv, nullptr, v, ROWS, DM, DM, 0);
    compute_M_kernel<<<BATCH * NH * SEQ, 32>>>(q, k, idx, Mb);
    topk_kernel<<<BATCH * NH, 256>>>(Mb, top);
    vmean_kernel<<<BATCH * NH, DK>>>(v, vm);
    fill_ctx_kernel<<<ELT_BLKS, 256>>>(vm, ctx);
    attn_update_kernel<<<BATCH * NH * NTOP, 256>>>(q, k, v, top, ctx);
    run_gemm(ctx, sa_wo, sa_bo, tgt, xin, ROWS, DM, DM, 0);
    bn_stats_kernel<<<DM, 256>>>(xin, mu, rs);
    bn_apply_kernel<<<ELT_BLKS, 256>>>(xin, mu, rs, bn1_g, bn1_b, x1);

    // ================= Cross-attention =================
    make_idx_kernel<<<IDX_BLKS, 256>>>(s2a, s2b, idx);
    run_gemm(x1,  ca_wq, ca_bq, nullptr, q, ROWS, DM, DM, 0);
    run_gemm(mem, ca_wk, ca_bk, nullptr, k, ROWS, DM, DM, 0);
    run_gemm(mem, ca_wv, ca_bv, nullptr, v, ROWS, DM, DM, 0);
    compute_M_kernel<<<BATCH * NH * SEQ, 32>>>(q, k, idx, Mb);
    topk_kernel<<<BATCH * NH, 256>>>(Mb, top);
    vmean_kernel<<<BATCH * NH, DK>>>(v, vm);
    fill_ctx_kernel<<<ELT_BLKS, 256>>>(vm, ctx);
    attn_update_kernel<<<BATCH * NH * NTOP, 256>>>(q, k, v, top, ctx);
    run_gemm(ctx, ca_wo, ca_bo, x1, xin, ROWS, DM, DM, 0);
    bn_stats_kernel<<<DM, 256>>>(xin, mu, rs);
    bn_apply_kernel<<<ELT_BLKS, 256>>>(xin, mu, rs, bn2_g, bn2_b, x2);

    // ================= FFN =================
    run_gemm(x2, w1, b1, nullptr, hbuf, ROWS, DFF, DM, 1);
    run_gemm(hbuf, w2, b2, x2, xin, ROWS, DM, DFF, 0);
    bn_stats_kernel<<<DM, 256>>>(xin, mu, rs);
    bn_apply_kernel<<<ELT_BLKS, 256>>>(xin, mu, rs, bn3_g, bn3_b, out);
}

// round 6
// speedup vs baseline: 3.7899x; 1.4898x over previous
#include <cuda_runtime.h>
#include <cstdint>
#include <math.h>

// ---------------------------------------------------------------------------
// Problem constants
// ---------------------------------------------------------------------------
#define RNG_PARTITIONABLE 1   // confirmed passing config -- do not change

constexpr int BATCH = 4, SEQ = 1024, DM = 1024, NH = 16, DK = 64, DFF = 4096;
constexpr int NSAMP = 35;
constexpr int NTOP  = 35;
constexpr int ROWS  = BATCH * SEQ;        // 4096
constexpr size_t NELEM = (size_t)ROWS * DM;
constexpr int IDX_N = SEQ * NSAMP;        // 35840
constexpr int IDX_HALF = IDX_N / 2;

// ---------------------------------------------------------------------------
// Static device scratch
// ---------------------------------------------------------------------------
__device__ float g_q[NELEM];
__device__ float g_k[NELEM];
__device__ float g_v[NELEM];
__device__ float g_ctx[NELEM];
__device__ float g_xin[NELEM];
__device__ float g_x1[NELEM];
__device__ float g_x2[NELEM];
__device__ float g_h[(size_t)ROWS * DFF];
__device__ float g_M[BATCH * NH * SEQ];
__device__ float g_vmean[BATCH * NH * DK];
__device__ int   g_top[BATCH * NH * NTOP];
__device__ int   g_idx[IDX_N];
__device__ float g_mu[DM];
__device__ float g_rstd[DM];
__device__ float g_bsum[DM];
__device__ float g_bsq[DM];

// ---------------------------------------------------------------------------
// TF32 input rounding (for FFMA-emulated einsums)
// ---------------------------------------------------------------------------
__device__ __forceinline__ float tf32r(float x) {
    uint32_t u;
    asm("cvt.rna.tf32.f32 %0, %1;" : "=r"(u) : "f"(x));
    return __uint_as_float(u);
}

__device__ __forceinline__ uint32_t saddr(const void* p) {
    return (uint32_t)__cvta_generic_to_shared(p);
}

__device__ __forceinline__ void cp16(uint32_t dst, const void* src) {
    asm volatile("cp.async.cg.shared.global [%0], [%1], 16;" :: "r"(dst), "l"(src));
}

// ---------------------------------------------------------------------------
// threefry2x32
// ---------------------------------------------------------------------------
__host__ __device__ __forceinline__ void tf2x32(uint32_t k0, uint32_t k1,
                                                uint32_t x0, uint32_t x1,
                                                uint32_t &o0, uint32_t &o1) {
    uint32_t ks2 = k0 ^ k1 ^ 0x1BD11BDAu;
    x0 += k0; x1 += k1;
#define TF_R(r) { x0 += x1; x1 = (x1 << (r)) | (x1 >> (32 - (r))); x1 ^= x0; }
    TF_R(13) TF_R(15) TF_R(26) TF_R(6)
    x0 += k1; x1 += ks2 + 1u;
    TF_R(17) TF_R(29) TF_R(16) TF_R(24)
    x0 += ks2; x1 += k0 + 2u;
    TF_R(13) TF_R(15) TF_R(26) TF_R(6)
    x0 += k0; x1 += k1 + 3u;
    TF_R(17) TF_R(29) TF_R(16) TF_R(24)
    x0 += k1; x1 += ks2 + 4u;
    TF_R(13) TF_R(15) TF_R(26) TF_R(6)
    x0 += ks2; x1 += k0 + 5u;
#undef TF_R
    o0 = x0; o1 = x1;
}

__global__ void make_idx_kernel(uint32_t ka, uint32_t kb, int* __restrict__ out) {
    int j = blockIdx.x * blockDim.x + threadIdx.x;
    if (j >= IDX_N) return;
    uint32_t o0, o1;
#if RNG_PARTITIONABLE
    tf2x32(ka, kb, 0u, (uint32_t)j, o0, o1);
    out[j] = (int)((o0 ^ o1) & 1023u);
#else
    if (j < IDX_HALF) {
        tf2x32(ka, kb, (uint32_t)j, (uint32_t)(IDX_HALF + j), o0, o1);
        out[j] = (int)(o0 & 1023u);
    } else {
        tf2x32(ka, kb, (uint32_t)(j - IDX_HALF), (uint32_t)j, o0, o1);
        out[j] = (int)(o1 & 1023u);
    }
#endif
}

// ---------------------------------------------------------------------------
// Tensor-core TF32 GEMM v2: cp.async double-buffered, BK=32.
// C = A[M,K] @ B[K,N] (+bias)(gelu?)(+resid).  HW truncates inputs to tf32.
// ---------------------------------------------------------------------------
constexpr int BM = 128, BN = 128, BK = 32;
constexpr int ASTR = 36;    // A smem row stride [m][k]: banks 4g+t, conflict-free
constexpr int BSTR = 136;   // B smem row stride [k][n]: banks 8t+g, conflict-free
constexpr int GEMM_SMEM = 2 * (BM * ASTR + BK * BSTR) * 4;   // 71680 B

__device__ __forceinline__ void mma_tf32(float c[4], uint32_t a0, uint32_t a1,
                                         uint32_t a2, uint32_t a3,
                                         uint32_t b0, uint32_t b1) {
    asm volatile(
        "mma.sync.aligned.m16n8k8.row.col.f32.tf32.tf32.f32 "
        "{%0,%1,%2,%3}, {%4,%5,%6,%7}, {%8,%9}, {%0,%1,%2,%3};"
        : "+f"(c[0]), "+f"(c[1]), "+f"(c[2]), "+f"(c[3])
        : "r"(a0), "r"(a1), "r"(a2), "r"(a3), "r"(b0), "r"(b1));
}

__global__ __launch_bounds__(256)
void gemm_tc_kernel(const float* __restrict__ A, const float* __restrict__ B,
                    const float* __restrict__ bias, const float* __restrict__ resid,
                    float* __restrict__ C, int M, int N, int K, int act) {
    extern __shared__ float gsm[];
    float* sA = gsm;                          // 2 stages of BM x ASTR
    float* sB = gsm + 2 * BM * ASTR;          // 2 stages of BK x BSTR

    const int tid  = threadIdx.x;
    const int lane = tid & 31, warp = tid >> 5;
    const int warpM = warp >> 2, warpN = warp & 3;   // 2 x 4 warps
    const int grp = lane >> 2, thr = lane & 3;
    const int row0 = blockIdx.y * BM;
    const int col0 = blockIdx.x * BN;

    float acc[4][4][4];
#pragma unroll
    for (int mt = 0; mt < 4; mt++)
#pragma unroll
        for (int nt = 0; nt < 4; nt++)
#pragma unroll
            for (int i = 0; i < 4; i++) acc[mt][nt][i] = 0.0f;

    const int T = K / BK;

    auto issue = [&](int t, int stage) {
        float* ad = sA + stage * (BM * ASTR);
        float* bd = sB + stage * (BK * BSTR);
#pragma unroll
        for (int i = 0; i < 4; i++) {
            int f = tid + i * 256;
            int ar = f >> 3, ac4 = f & 7;       // 128 rows x 8 chunks
            cp16(saddr(ad + ar * ASTR + ac4 * 4),
                 &A[(size_t)(row0 + ar) * K + t * BK + ac4 * 4]);
            int br = f >> 5, bc4 = f & 31;      // 32 rows x 32 chunks
            cp16(saddr(bd + br * BSTR + bc4 * 4),
                 &B[(size_t)(t * BK + br) * N + col0 + bc4 * 4]);
        }
        asm volatile("cp.async.commit_group;");
    };

    issue(0, 0);

    for (int t = 0; t < T; t++) {
        const int cur = t & 1;
        if (t + 1 < T) {
            issue(t + 1, (t + 1) & 1);
            asm volatile("cp.async.wait_group 1;");
        } else {
            asm volatile("cp.async.wait_group 0;");
        }
        __syncthreads();

        const float* sAc = sA + cur * (BM * ASTR);
        const float* sBc = sB + cur * (BK * BSTR);
#pragma unroll
        for (int ks = 0; ks < 4; ks++) {
            const int kk = ks * 8;
            uint32_t a[4][4], b[4][2];
#pragma unroll
            for (int mt = 0; mt < 4; mt++) {
                int mb = warpM * 64 + mt * 16 + grp;
                a[mt][0] = __float_as_uint(sAc[mb * ASTR + kk + thr]);
                a[mt][1] = __float_as_uint(sAc[(mb + 8) * ASTR + kk + thr]);
                a[mt][2] = __float_as_uint(sAc[mb * ASTR + kk + thr + 4]);
                a[mt][3] = __float_as_uint(sAc[(mb + 8) * ASTR + kk + thr + 4]);
            }
#pragma unroll
            for (int nt = 0; nt < 4; nt++) {
                int nb = warpN * 32 + nt * 8 + grp;
                b[nt][0] = __float_as_uint(sBc[(kk + thr) * BSTR + nb]);
                b[nt][1] = __float_as_uint(sBc[(kk + thr + 4) * BSTR + nb]);
            }
#pragma unroll
            for (int mt = 0; mt < 4; mt++)
#pragma unroll
                for (int nt = 0; nt < 4; nt++)
                    mma_tf32(acc[mt][nt], a[mt][0], a[mt][1], a[mt][2], a[mt][3],
                             b[nt][0], b[nt][1]);
        }
        __syncthreads();
    }

#pragma unroll
    for (int mt = 0; mt < 4; mt++) {
#pragma unroll
        for (int nt = 0; nt < 4; nt++) {
#pragma unroll
            for (int half = 0; half < 2; half++) {
                int m = row0 + warpM * 64 + mt * 16 + grp + half * 8;
                int n = col0 + warpN * 32 + nt * 8 + thr * 2;
#pragma unroll
                for (int c = 0; c < 2; c++) {
                    float vv = acc[mt][nt][half * 2 + c];
                    int nn = n + c;
                    if (bias) vv += bias[nn];
                    if (act) vv = 0.5f * vv * (1.0f + erff(vv * 0.70710678118654752f));
                    if (resid) vv += resid[(size_t)m * N + nn];
                    C[(size_t)m * N + nn] = vv;
                }
            }
        }
    }
}

// ---------------------------------------------------------------------------
// M[b,h,l]: one warp per (b,h,l), fp32
// ---------------------------------------------------------------------------
__global__ void compute_M_kernel(const float* __restrict__ Q, const float* __restrict__ Kp,
                                 const int* __restrict__ idx, float* __restrict__ Mout) {
    int bhl = blockIdx.x;
    int l = bhl & (SEQ - 1);
    int bh = bhl >> 10;
    int h = bh & (NH - 1);
    int b = bh >> 4;
    int lane = threadIdx.x;

    const float* q = Q + ((size_t)(b * SEQ + l)) * DM + h * DK;
    float q0 = q[lane], q1 = q[lane + 32];
    float mx = -1e38f, sm = 0.0f;
    const int* row = idx + l * NSAMP;
#pragma unroll 1
    for (int s = 0; s < NSAMP; s++) {
        int ki = row[s];
        const float* kr = Kp + ((size_t)(b * SEQ + ki)) * DM + h * DK;
        float p = q0 * kr[lane] + q1 * kr[lane + 32];
#pragma unroll
        for (int o = 16; o; o >>= 1) p += __shfl_xor_sync(0xffffffffu, p, o);
        mx = fmaxf(mx, p);
        sm += p;
    }
    if (lane == 0) Mout[bhl] = mx - sm * (1.0f / (float)SEQ);
}

// ---------------------------------------------------------------------------
// top-35 per (b,h)
// ---------------------------------------------------------------------------
__global__ void topk_kernel(const float* __restrict__ Min, int* __restrict__ top) {
    int bh = blockIdx.x;
    int tid = threadIdx.x;
    __shared__ float vals[SEQ];
    __shared__ float rv[256];
    __shared__ int   ri[256];

    for (int i = tid; i < SEQ; i += 256) vals[i] = Min[(size_t)bh * SEQ + i];
    __syncthreads();

    for (int u = 0; u < NTOP; u++) {
        float bv = -1e38f; int bi = 0x7fffffff;
        for (int i = tid; i < SEQ; i += 256) {
            float vv = vals[i];
            if (vv > bv || (vv == bv && i < bi)) { bv = vv; bi = i; }
        }
        rv[tid] = bv; ri[tid] = bi;
        __syncthreads();
        for (int o = 128; o; o >>= 1) {
            if (tid < o) {
                if (rv[tid + o] > rv[tid] ||
                    (rv[tid + o] == rv[tid] && ri[tid + o] < ri[tid])) {
                    rv[tid] = rv[tid + o]; ri[tid] = ri[tid + o];
                }
            }
            __syncthreads();
        }
        if (tid == 0) { top[bh * NTOP + u] = ri[0]; vals[ri[0]] = -1e38f; }
        __syncthreads();
    }
}

// ---------------------------------------------------------------------------
// vmean + ctx broadcast fill (float4)
// ---------------------------------------------------------------------------
__global__ void vmean_kernel(const float* __restrict__ V, float* __restrict__ vmean) {
    int bh = blockIdx.x;
    int b = bh >> 4, h = bh & (NH - 1);
    int d = threadIdx.x;
    const float* base = V + ((size_t)b * SEQ) * DM + h * DK + d;
    float s = 0.0f;
    for (int i = 0; i < SEQ; i++) s += base[(size_t)i * DM];
    vmean[bh * DK + d] = s * (1.0f / (float)SEQ);
}

__global__ void fill_ctx4_kernel(const float* __restrict__ vmean, float* __restrict__ ctx) {
    size_t i = (size_t)blockIdx.x * 256 + threadIdx.x;     // over NELEM/4
    int c4 = (int)(i & 255);
    int b = (int)(i >> 18);                                // SEQ*DM/4 = 2^18
    int h = c4 >> 4;
    ((float4*)ctx)[i] = ((const float4*)vmean)[(b * NH + h) * 16 + (c4 & 15)];
}

// ---------------------------------------------------------------------------
// attn v2: one block per (b,h). Scores (35x1024) in dynamic smem; K/V tiled.
// ---------------------------------------------------------------------------
constexpr int KTILE = 64;
constexpr int KSTR = 65;
constexpr int QSTR = 65;
// layout (floats): qs[35*65]=2275 pad->2280 | rden[35] pad->40 | ks[64*65]=4160 | sc[35*1024]
constexpr int OFF_RDEN = 2280;
constexpr int OFF_KS   = 2320;
constexpr int OFF_SC   = 2320 + 4160;       // 6480
constexpr int ATTN_SMEM = (OFF_SC + NTOP * SEQ) * 4;   // 169280 B

__global__ __launch_bounds__(256)
void attn_bh_kernel(const float* __restrict__ Q, const float* __restrict__ Kp,
                    const float* __restrict__ V, const int* __restrict__ top,
                    float* __restrict__ ctx) {
    extern __shared__ float dsm[];
    float* qs   = dsm;
    float* rden = dsm + OFF_RDEN;
    float* ks   = dsm + OFF_KS;
    float* sc   = dsm + OFF_SC;

    int bh = blockIdx.x;
    int b = bh >> 4, h = bh & (NH - 1);
    int tid = threadIdx.x;
    int lane = tid & 31, warp = tid >> 5;

    // load top-35 q rows (tf32-rounded)
    for (int i = tid; i < NTOP * DK; i += 256) {
        int u = i >> 6, d = i & 63;
        int qr = top[bh * NTOP + u];
        qs[u * QSTR + d] = tf32r(Q[((size_t)(b * SEQ + qr)) * DM + h * DK + d]);
    }
    __syncthreads();

    // scores
    for (int kt = 0; kt < SEQ / KTILE; kt++) {
        for (int i = tid; i < KTILE * DK / 4; i += 256) {
            int key = i >> 4, d4 = i & 15;
            float4 vv = *(const float4*)&Kp[((size_t)(b * SEQ + kt * KTILE + key)) * DM + h * DK + d4 * 4];
            float* dst = &ks[key * KSTR + d4 * 4];
            dst[0] = tf32r(vv.x); dst[1] = tf32r(vv.y);
            dst[2] = tf32r(vv.z); dst[3] = tf32r(vv.w);
        }
        __syncthreads();
        for (int p = tid; p < NTOP * KTILE; p += 256) {
            int u = p >> 6, key = p & 63;
            float a = 0.0f;
#pragma unroll
            for (int dd = 0; dd < DK; dd++) a += qs[u * QSTR + dd] * ks[key * KSTR + dd];
            sc[u * SEQ + kt * KTILE + key] = a * 0.125f;
        }
        __syncthreads();
    }

    // softmax per u row (warp per row)
    for (int u = warp; u < NTOP; u += 8) {
        float m = -1e38f;
        for (int i = lane; i < SEQ; i += 32) m = fmaxf(m, sc[u * SEQ + i]);
#pragma unroll
        for (int o = 16; o; o >>= 1) m = fmaxf(m, __shfl_xor_sync(0xffffffffu, m, o));
        float s = 0.0f;
        for (int i = lane; i < SEQ; i += 32) {
            float e = expf(sc[u * SEQ + i] - m);
            sc[u * SEQ + i] = e;
            s += e;
        }
#pragma unroll
        for (int o = 16; o; o >>= 1) s += __shfl_xor_sync(0xffffffffu, s, o);
        if (lane == 0) rden[u] = 1.0f / s;
    }
    __syncthreads();

    // normalize + tf32-round attn in place
    for (int f = tid; f < NTOP * SEQ; f += 256) {
        int u = f >> 10;
        sc[f] = tf32r(sc[f] * rden[u]);
    }
    __syncthreads();

    // upd = attn @ V
    float accv[9];
#pragma unroll
    for (int j = 0; j < 9; j++) accv[j] = 0.0f;

    for (int kt = 0; kt < SEQ / KTILE; kt++) {
        for (int i = tid; i < KTILE * DK / 4; i += 256) {
            int key = i >> 4, d4 = i & 15;
            float4 vv = *(const float4*)&V[((size_t)(b * SEQ + kt * KTILE + key)) * DM + h * DK + d4 * 4];
            float* dst = &ks[key * KSTR + d4 * 4];
            dst[0] = tf32r(vv.x); dst[1] = tf32r(vv.y);
            dst[2] = tf32r(vv.z); dst[3] = tf32r(vv.w);
        }
        __syncthreads();
        int j = 0;
        for (int p = tid; p < NTOP * DK; p += 256, j++) {
            int u = p >> 6, d = p & 63;
            float a = accv[j];
            const float* srow = &sc[u * SEQ + kt * KTILE];
#pragma unroll
            for (int key = 0; key < KTILE; key++)
                a += srow[key] * ks[key * KSTR + d];
            accv[j] = a;
        }
        __syncthreads();
    }

    int j = 0;
    for (int p = tid; p < NTOP * DK; p += 256, j++) {
        int u = p >> 6, d = p & 63;
        int qr = top[bh * NTOP + u];
        ctx[((size_t)(b * SEQ + qr)) * DM + h * DK + d] = accv[j];
    }
}

// ---------------------------------------------------------------------------
// BatchNorm v2: coalesced one-pass partials + atomics
// ---------------------------------------------------------------------------
__global__ void bn_zero_kernel() {
    int i = blockIdx.x * 256 + threadIdx.x;
    if (i < DM) { g_bsum[i] = 0.0f; g_bsq[i] = 0.0f; }
}

__global__ void bn_partial_kernel(const float* __restrict__ x) {
    int blk = blockIdx.x;          // 64 blocks x 64 rows
    int tid = threadIdx.x;
    float s[4] = {0, 0, 0, 0}, q[4] = {0, 0, 0, 0};
    const float* base = x + (size_t)blk * 64 * DM;
    for (int r = 0; r < 64; r++) {
#pragma unroll
        for (int j = 0; j < 4; j++) {
            float v = base[(size_t)r * DM + tid + j * 256];
            s[j] += v; q[j] += v * v;
        }
    }
#pragma unroll
    for (int j = 0; j < 4; j++) {
        atomicAdd(&g_bsum[tid + j * 256], s[j]);
        atomicAdd(&g_bsq[tid + j * 256], q[j]);
    }
}

__global__ void bn_final_kernel(float* __restrict__ mu, float* __restrict__ rstd) {
    int c = blockIdx.x * 256 + threadIdx.x;
    if (c < DM) {
        float m = g_bsum[c] * (1.0f / (float)ROWS);
        float v = g_bsq[c] * (1.0f / (float)ROWS) - m * m;
        mu[c] = m;
        rstd[c] = rsqrtf(v + 1e-5f);
    }
}

__global__ void bn_apply4_kernel(const float* __restrict__ x, const float* __restrict__ mu,
                                 const float* __restrict__ rstd, const float* __restrict__ g,
                                 const float* __restrict__ bta, float* __restrict__ y) {
    size_t i = (size_t)blockIdx.x * 256 + threadIdx.x;   // over NELEM/4
    int c4 = (int)(i & 255);
    float4 xv = ((const float4*)x)[i];
    float4 m = ((const float4*)mu)[c4];
    float4 r = ((const float4*)rstd)[c4];
    float4 gg = ((const float4*)g)[c4];
    float4 bb = ((const float4*)bta)[c4];
    float4 o;
    o.x = (xv.x - m.x) * r.x * gg.x + bb.x;
    o.y = (xv.y - m.y) * r.y * gg.y + bb.y;
    o.z = (xv.z - m.z) * r.z * gg.z + bb.z;
    o.w = (xv.w - m.w) * r.w * gg.w + bb.w;
    ((float4*)y)[i] = o;
}

// ---------------------------------------------------------------------------
// Launch helpers
// ---------------------------------------------------------------------------
static void run_gemm(const float* A, const float* B, const float* bias,
                     const float* resid, float* C, int M, int N, int K, int act) {
    dim3 grid(N / BN, M / BM);
    gemm_tc_kernel<<<grid, 256, GEMM_SMEM>>>(A, B, bias, resid, C, M, N, K, act);
}

static void run_bn(const float* x, float* mu, float* rs,
                   const float* g, const float* bta, float* y) {
    bn_zero_kernel<<<4, 256>>>();
    bn_partial_kernel<<<64, 256>>>(x);
    bn_final_kernel<<<4, 256>>>(mu, rs);
    bn_apply4_kernel<<<(int)(NELEM / 4 / 256), 256>>>(x, mu, rs, g, bta, y);
}

extern "C" void kernel_launch(void* const* d_in, const int* in_sizes, int n_in,
                              void* d_out, int out_size) {
    const float* tgt   = (const float*)d_in[0];
    const float* mem   = (const float*)d_in[1];
    const float* sa_wq = (const float*)d_in[2];
    const float* sa_bq = (const float*)d_in[3];
    const float* sa_wk = (const float*)d_in[4];
    const float* sa_bk = (const float*)d_in[5];
    const float* sa_wv = (const float*)d_in[6];
    const float* sa_bv = (const float*)d_in[7];
    const float* sa_wo = (const float*)d_in[8];
    const float* sa_bo = (const float*)d_in[9];
    const float* ca_wq = (const float*)d_in[10];
    const float* ca_bq = (const float*)d_in[11];
    const float* ca_wk = (const float*)d_in[12];
    const float* ca_bk = (const float*)d_in[13];
    const float* ca_wv = (const float*)d_in[14];
    const float* ca_bv = (const float*)d_in[15];
    const float* ca_wo = (const float*)d_in[16];
    const float* ca_bo = (const float*)d_in[17];
    const float* w1    = (const float*)d_in[18];
    const float* b1    = (const float*)d_in[19];
    const float* w2    = (const float*)d_in[20];
    const float* b2    = (const float*)d_in[21];
    const float* bn1_g = (const float*)d_in[22];
    const float* bn1_b = (const float*)d_in[23];
    const float* bn2_g = (const float*)d_in[24];
    const float* bn2_b = (const float*)d_in[25];
    const float* bn3_g = (const float*)d_in[26];
    const float* bn3_b = (const float*)d_in[27];
    float* out = (float*)d_out;

    cudaFuncSetAttribute(gemm_tc_kernel, cudaFuncAttributeMaxDynamicSharedMemorySize, GEMM_SMEM);
    cudaFuncSetAttribute(attn_bh_kernel, cudaFuncAttributeMaxDynamicSharedMemorySize, ATTN_SMEM);

    float *q, *k, *v, *ctx, *xin, *x1, *x2, *hbuf, *Mb, *vm, *mu, *rs;
    int *top, *idx;
    cudaGetSymbolAddress((void**)&q,    g_q);
    cudaGetSymbolAddress((void**)&k,    g_k);
    cudaGetSymbolAddress((void**)&v,    g_v);
    cudaGetSymbolAddress((void**)&ctx,  g_ctx);
    cudaGetSymbolAddress((void**)&xin,  g_xin);
    cudaGetSymbolAddress((void**)&x1,   g_x1);
    cudaGetSymbolAddress((void**)&x2,   g_x2);
    cudaGetSymbolAddress((void**)&hbuf, g_h);
    cudaGetSymbolAddress((void**)&Mb,   g_M);
    cudaGetSymbolAddress((void**)&vm,   g_vmean);
    cudaGetSymbolAddress((void**)&top,  g_top);
    cudaGetSymbolAddress((void**)&idx,  g_idx);
    cudaGetSymbolAddress((void**)&mu,   g_mu);
    cudaGetSymbolAddress((void**)&rs,   g_rstd);

    // Key derivation (frozen): root=key(42); k1,k2=split(root); randint uses split(rng)[1]
    uint32_t r1a, r1b, r2a, r2b;
    uint32_t s1a, s1b, s2a, s2b;
#if RNG_PARTITIONABLE
    tf2x32(0u, 42u, 0u, 0u, r1a, r1b);
    tf2x32(0u, 42u, 0u, 1u, r2a, r2b);
    tf2x32(r1a, r1b, 0u, 1u, s1a, s1b);
    tf2x32(r2a, r2b, 0u, 1u, s2a, s2b);
#else
    {
        uint32_t a0, b0, a1, b1;
        tf2x32(0u, 42u, 0u, 2u, a0, b0);
        tf2x32(0u, 42u, 1u, 3u, a1, b1);
        r1a = a0; r1b = a1;
        r2a = b0; r2b = b1;
        tf2x32(r1a, r1b, 0u, 2u, a0, b0);
        tf2x32(r1a, r1b, 1u, 3u, a1, b1);
        s1a = b0; s1b = b1;
        tf2x32(r2a, r2b, 0u, 2u, a0, b0);
        tf2x32(r2a, r2b, 1u, 3u, a1, b1);
        s2a = b0; s2b = b1;
    }
#endif

    const int ELT4_BLKS = (int)(NELEM / 4 / 256);
    const int IDX_BLKS = (IDX_N + 255) / 256;

    // ================= Self-attention =================
    make_idx_kernel<<<IDX_BLKS, 256>>>(s1a, s1b, idx);
    run_gemm(tgt, sa_wq, sa_bq, nullptr, q, ROWS, DM, DM, 0);
    run_gemm(tgt, sa_wk, sa_bk, nullptr, k, ROWS, DM, DM, 0);
    run_gemm(tgt, sa_wv, sa_bv, nullptr, v, ROWS, DM, DM, 0);
    compute_M_kernel<<<BATCH * NH * SEQ, 32>>>(q, k, idx, Mb);
    topk_kernel<<<BATCH * NH, 256>>>(Mb, top);
    vmean_kernel<<<BATCH * NH, DK>>>(v, vm);
    fill_ctx4_kernel<<<ELT4_BLKS, 256>>>(vm, ctx);
    attn_bh_kernel<<<BATCH * NH, 256, ATTN_SMEM>>>(q, k, v, top, ctx);
    run_gemm(ctx, sa_wo, sa_bo, tgt, xin, ROWS, DM, DM, 0);
    run_bn(xin, mu, rs, bn1_g, bn1_b, x1);

    // ================= Cross-attention =================
    make_idx_kernel<<<IDX_BLKS, 256>>>(s2a, s2b, idx);
    run_gemm(x1,  ca_wq, ca_bq, nullptr, q, ROWS, DM, DM, 0);
    run_gemm(mem, ca_wk, ca_bk, nullptr, k, ROWS, DM, DM, 0);
    run_gemm(mem, ca_wv, ca_bv, nullptr, v, ROWS, DM, DM, 0);
    compute_M_kernel<<<BATCH * NH * SEQ, 32>>>(q, k, idx, Mb);
    topk_kernel<<<BATCH * NH, 256>>>(Mb, top);
    vmean_kernel<<<BATCH * NH, DK>>>(v, vm);
    fill_ctx4_kernel<<<ELT4_BLKS, 256>>>(vm, ctx);
    attn_bh_kernel<<<BATCH * NH, 256, ATTN_SMEM>>>(q, k, v, top, ctx);
    run_gemm(ctx, ca_wo, ca_bo, x1, xin, ROWS, DM, DM, 0);
    run_bn(xin, mu, rs, bn2_g, bn2_b, x2);

    // ================= FFN =================
    run_gemm(x2, w1, b1, nullptr, hbuf, ROWS, DFF, DM, 1);
    run_gemm(hbuf, w2, b2, x2, xin, ROWS, DM, DFF, 0);
    run_bn(xin, mu, rs, bn3_g, bn3_b, out);
}